// round 13
// baseline (speedup 1.0000x reference)
#include <cuda.h>
#include <cuda_runtime.h>
#include <cuda_bf16.h>
#include <cuda_fp16.h>
#include <cstdint>

// ============================================================================
// y[8192,4096] = mean(|W|) * (x[8192,4096] @ sign(W)[4096,4096]^T)
// Round 13: persistent-CTA version of the R12 GEMM. Each CTA processes tiles
// with stride gridDim.x; next tile's stage-0/1 cp.async issued BEFORE the
// current tile's epilogue stores (refill/store overlap). Named-barrier
// pipeline with tail guards + per-tile EMPTY drain. Prep as R11/R12.
// ============================================================================

#define M_TOTAL 8192
#define N_TOTAL 4096
#define K_TOTAL 4096

#define CTA_M 128
#define CTA_N 128
#define K_STEP 64
#define NKT (K_TOTAL / K_STEP)   // 64
#define STAGES 3
#define NTILES 2048              // 64 mtiles x 32 ntiles

#define OFF_A 0
#define OFF_B 16384
#define STAGE_BYTES 32768
#define SMEM_RED (STAGES * STAGE_BYTES)          // 1KB reduction buffer after stages
#define SMEM_TOTAL (SMEM_RED + 1024)             // 99328 -> still 2 CTAs/SM

// ---------------------------------------------------------------------------
// Device scratch (allocation-free rule: __device__ globals)
// ---------------------------------------------------------------------------
__device__ __align__(1024) __half g_Ah[(size_t)M_TOTAL * K_TOTAL];
__device__ __align__(1024) __half g_Bsign[(size_t)N_TOTAL * K_TOTAL];
__device__ float g_partials[1024];

// ---------------------------------------------------------------------------
// PTX helpers
// ---------------------------------------------------------------------------
__device__ __forceinline__ uint32_t smem_to_u32(const void* p) {
    uint32_t a;
    asm("{ .reg .u64 t; cvta.to.shared.u64 t, %1; cvt.u32.u64 %0, t; }" : "=r"(a) : "l"(p));
    return a;
}

__device__ __forceinline__ void cp_async16(uint32_t dst, const void* src) {
    asm volatile("cp.async.cg.shared.global [%0], [%1], 16;" :: "r"(dst), "l"(src) : "memory");
}
__device__ __forceinline__ void cp_commit() {
    asm volatile("cp.async.commit_group;" ::: "memory");
}
template <int N>
__device__ __forceinline__ void cp_wait() {
    asm volatile("cp.async.wait_group %0;" :: "n"(N) : "memory");
}

// Named barriers: 256 non-blocking arrivals + 256 blocking syncs = count 512.
__device__ __forceinline__ void bar_arrive_id(uint32_t id) {
    asm volatile("bar.arrive %0, 512;" :: "r"(id));
}
__device__ __forceinline__ void bar_sync_id(uint32_t id) {
    asm volatile("bar.sync %0, 512;" :: "r"(id) : "memory");
}

__device__ __forceinline__ void ldmatrix_x4(uint32_t& r0, uint32_t& r1,
                                            uint32_t& r2, uint32_t& r3, uint32_t addr) {
    asm volatile("ldmatrix.sync.aligned.m8n8.x4.shared.b16 {%0,%1,%2,%3}, [%4];"
                 : "=r"(r0), "=r"(r1), "=r"(r2), "=r"(r3) : "r"(addr));
}

__device__ __forceinline__ void mma16816(float& d0, float& d1, float& d2, float& d3,
                                         uint32_t a0, uint32_t a1, uint32_t a2, uint32_t a3,
                                         uint32_t b0, uint32_t b1) {
    asm volatile(
        "mma.sync.aligned.m16n8k16.row.col.f32.f16.f16.f32 "
        "{%0,%1,%2,%3}, {%4,%5,%6,%7}, {%8,%9}, {%0,%1,%2,%3};"
        : "+f"(d0), "+f"(d1), "+f"(d2), "+f"(d3)
        : "r"(a0), "r"(a1), "r"(a2), "r"(a3), "r"(b0), "r"(b1));
}

// ---------------------------------------------------------------------------
// Merged prep kernel (R11), grid 3072 x 256
// ---------------------------------------------------------------------------
__global__ void prep_kernel(const float* __restrict__ W, const float* __restrict__ x) {
    if (blockIdx.x < 1024) {
        __shared__ float sdata[256];
        const size_t base4 = (size_t)blockIdx.x * 4096;
        float s = 0.0f;
        #pragma unroll 4
        for (int it = 0; it < 16; it++) {
            size_t i = base4 + threadIdx.x + it * 256;
            float4 v = reinterpret_cast<const float4*>(W)[i];
            s += fabsf(v.x) + fabsf(v.y) + fabsf(v.z) + fabsf(v.w);
            float sx = (v.x > 0.0f) ? 1.0f : ((v.x < 0.0f) ? -1.0f : 0.0f);
            float sy = (v.y > 0.0f) ? 1.0f : ((v.y < 0.0f) ? -1.0f : 0.0f);
            float sz = (v.z > 0.0f) ? 1.0f : ((v.z < 0.0f) ? -1.0f : 0.0f);
            float sw = (v.w > 0.0f) ? 1.0f : ((v.w < 0.0f) ? -1.0f : 0.0f);
            ushort4 o = make_ushort4(__half_as_ushort(__float2half(sx)),
                                     __half_as_ushort(__float2half(sy)),
                                     __half_as_ushort(__float2half(sz)),
                                     __half_as_ushort(__float2half(sw)));
            reinterpret_cast<ushort4*>(g_Bsign)[i] = o;
        }
        sdata[threadIdx.x] = s;
        __syncthreads();
        for (int off = 128; off > 0; off >>= 1) {
            if (threadIdx.x < off) sdata[threadIdx.x] += sdata[threadIdx.x + off];
            __syncthreads();
        }
        if (threadIdx.x == 0) g_partials[blockIdx.x] = sdata[0];
    } else {
        const size_t base4 = (size_t)(blockIdx.x - 1024) * 4096;
        #pragma unroll 4
        for (int it = 0; it < 16; it++) {
            size_t i = base4 + threadIdx.x + it * 256;
            float4 v = reinterpret_cast<const float4*>(x)[i];
            ushort4 hv = make_ushort4(__half_as_ushort(__float2half_rn(v.x)),
                                      __half_as_ushort(__float2half_rn(v.y)),
                                      __half_as_ushort(__float2half_rn(v.z)),
                                      __half_as_ushort(__float2half_rn(v.w)));
            reinterpret_cast<ushort4*>(g_Ah)[i] = hv;
        }
    }
}

// ---------------------------------------------------------------------------
// Persistent GEMM kernel: CTA 128x128, 8 warps (2M x 4N), warp tile 64x32.
// FULL[s] = barrier 1+s, EMPTY[s] = barrier 4+s (count 512).
// ---------------------------------------------------------------------------
__global__ void __launch_bounds__(256, 2) gemm_kernel(float* __restrict__ out) {
    extern __shared__ __align__(128) char smem[];
    const uint32_t smem_base = smem_to_u32(smem);

    const int tid = threadIdx.x;
    const int lane = tid & 31;
    const int wid = tid >> 5;
    const int wm = wid & 1;
    const int wn = wid >> 1;

    // ---- per-thread cp.async invariants ----
    const int cquad = tid & 7;
    const int row0 = tid >> 3;
    const uint32_t csw16 = (uint32_t)((cquad ^ (row0 & 7)) * 16);
    const char* baseA = (const char*)g_Ah + (size_t)row0 * 8192 + cquad * 16;
    const char* baseB = (const char*)g_Bsign + (size_t)row0 * 8192 + cquad * 16;
    const uint32_t dA = (uint32_t)(OFF_A + row0 * 128) + csw16;
    const uint32_t dB = (uint32_t)(OFF_B + row0 * 128) + csw16;

    auto load_stage = [&](const char* pA, const char* pB, int s, int kt) {
        const uint32_t st = smem_base + s * STAGE_BYTES;
        const size_t kb = (size_t)kt * 128;
        #pragma unroll
        for (int i = 0; i < 4; i++)
            cp_async16(st + dA + i * 32 * 128, pA + (size_t)i * 32 * 8192 + kb);
        #pragma unroll
        for (int i = 0; i < 4; i++)
            cp_async16(st + dB + i * 32 * 128, pB + (size_t)i * 32 * 8192 + kb);
        cp_commit();
    };

    // ---- ldmatrix per-lane addressing ----
    const uint32_t lo7 = (uint32_t)(lane & 7);
    const uint32_t aHi = (uint32_t)(lane >> 4);
    const uint32_t bHi = (uint32_t)((lane >> 3) & 1);
    uint32_t aRowOff[4];
    #pragma unroll
    for (int i = 0; i < 4; i++)
        aRowOff[i] = (uint32_t)(OFF_A + (wm * 64 + i * 16 + (lane & 15)) * 128);
    uint32_t bRowOff[2];
    #pragma unroll
    for (int j2 = 0; j2 < 2; j2++)
        bRowOff[j2] = (uint32_t)(OFF_B + (wn * 32 + (lane & 7) +
                                          ((lane >> 4) & 1) * 8 + j2 * 16) * 128);

    // ---- first tile prologue: start loads, then scale reduction overlaps ----
    int tile = blockIdx.x;
    const char* curA = baseA + (size_t)(tile >> 5) * 128 * 8192;
    const char* curB = baseB + (size_t)(tile & 31) * 128 * 8192;
    load_stage(curA, curB, 0, 0);
    load_stage(curA, curB, 1, 1);

    // scale reduction in dedicated smem region (overlaps the first loads)
    float* sred = reinterpret_cast<float*>(smem + SMEM_RED);
    {
        float s = 0.0f;
        #pragma unroll
        for (int i = 0; i < 4; i++) s += g_partials[tid * 4 + i];
        sred[tid] = s;
    }
    __syncthreads();
    for (int off = 128; off > 0; off >>= 1) {
        if (tid < off) sred[tid] += sred[tid + off];
        __syncthreads();
    }
    const float scl = sred[0] * (1.0f / 16777216.0f);

    cp_wait<1>();
    bar_arrive_id(1 + 0);   // FULL[0]
    bar_arrive_id(4 + 2);   // EMPTY[2] seed

    float acc[4][4][4];

    while (true) {
        #pragma unroll
        for (int i = 0; i < 4; i++)
            #pragma unroll
            for (int j = 0; j < 4; j++)
                #pragma unroll
                for (int r = 0; r < 4; r++) acc[i][j][r] = 0.0f;

        int s_cons = 0;
        for (int kt = 0; kt < NKT; kt++) {
            int s_load = s_cons + 2; if (s_load >= STAGES) s_load -= STAGES;
            int s_next = s_cons + 1; if (s_next >= STAGES) s_next -= STAGES;

            bar_sync_id(1 + (uint32_t)s_cons);       // FULL[s_cons]
            const uint32_t st = smem_base + s_cons * STAGE_BYTES;

            #pragma unroll
            for (int kk = 0; kk < 2; kk++) {
                const uint32_t aC = ((uint32_t)(kk * 2) + aHi) ^ lo7;
                const uint32_t bC = ((uint32_t)(kk * 2) + bHi) ^ lo7;
                uint32_t bq[8];
                #pragma unroll
                for (int j2 = 0; j2 < 2; j2++)
                    ldmatrix_x4(bq[4 * j2], bq[4 * j2 + 1], bq[4 * j2 + 2], bq[4 * j2 + 3],
                                st + bRowOff[j2] + bC * 16);
                #pragma unroll
                for (int i = 0; i < 4; i++) {
                    uint32_t a0, a1, a2, a3;
                    ldmatrix_x4(a0, a1, a2, a3, st + aRowOff[i] + aC * 16);
                    #pragma unroll
                    for (int j = 0; j < 4; j++)
                        mma16816(acc[i][j][0], acc[i][j][1], acc[i][j][2], acc[i][j][3],
                                 a0, a1, a2, a3, bq[2 * j], bq[2 * j + 1]);
                }
            }

            if (kt < NKT - 2) {
                bar_sync_id(4 + (uint32_t)s_load);   // EMPTY[s_load]
                load_stage(curA, curB, s_load, kt + 2);
            } else {
                cp_commit();                          // empty group
            }
            if (kt < NKT - 1) {
                cp_wait<1>();
                bar_arrive_id(1 + (uint32_t)s_next);  // FULL[kt+1]
            } else {
                cp_wait<0>();
            }

            #pragma unroll
            for (int kk = 2; kk < 4; kk++) {
                const uint32_t aC = ((uint32_t)(kk * 2) + aHi) ^ lo7;
                const uint32_t bC = ((uint32_t)(kk * 2) + bHi) ^ lo7;
                uint32_t bq[8];
                #pragma unroll
                for (int j2 = 0; j2 < 2; j2++)
                    ldmatrix_x4(bq[4 * j2], bq[4 * j2 + 1], bq[4 * j2 + 2], bq[4 * j2 + 3],
                                st + bRowOff[j2] + bC * 16);
                #pragma unroll
                for (int i = 0; i < 4; i++) {
                    uint32_t a0, a1, a2, a3;
                    ldmatrix_x4(a0, a1, a2, a3, st + aRowOff[i] + aC * 16);
                    #pragma unroll
                    for (int j = 0; j < 4; j++)
                        mma16816(acc[i][j][0], acc[i][j][1], acc[i][j][2], acc[i][j][3],
                                 a0, a1, a2, a3, bq[2 * j], bq[2 * j + 1]);
                }
            }

            bar_arrive_id(4 + (uint32_t)s_cons);      // EMPTY[s_cons]
            s_cons = s_next;
        }

        // drain pending EMPTY arrivals (from kt = NKT-3..NKT-1) -> neutral
        bar_sync_id(4 + 0);
        bar_sync_id(4 + 1);
        bar_sync_id(4 + 2);

        // ---- next tile prefetch BEFORE this tile's stores ----
        const int next = tile + (int)gridDim.x;
        const bool more = (next < NTILES);
        const char* nxtA = curA; const char* nxtB = curB;
        if (more) {
            nxtA = baseA + (size_t)(next >> 5) * 128 * 8192;
            nxtB = baseB + (size_t)(next & 31) * 128 * 8192;
            load_stage(nxtA, nxtB, 0, 0);
            load_stage(nxtA, nxtB, 1, 1);
        }

        // ---- epilogue stores for current tile (overlap the prefetch) ----
        {
            const int mbase = (tile >> 5) * 128 + wm * 64 + (lane >> 2);
            const int nbase = (tile & 31) * 128 + wn * 32 + (lane & 3) * 2;
            #pragma unroll
            for (int i = 0; i < 4; i++) {
                const int r0 = mbase + i * 16;
                #pragma unroll
                for (int j = 0; j < 4; j++) {
                    const int c = nbase + j * 8;
                    float2 v0 = make_float2(acc[i][j][0] * scl, acc[i][j][1] * scl);
                    float2 v1 = make_float2(acc[i][j][2] * scl, acc[i][j][3] * scl);
                    *reinterpret_cast<float2*>(out + (size_t)r0 * N_TOTAL + c) = v0;
                    *reinterpret_cast<float2*>(out + (size_t)(r0 + 8) * N_TOTAL + c) = v1;
                }
            }
        }

        if (!more) break;
        cp_wait<1>();
        bar_arrive_id(1 + 0);   // FULL[0] for next tile
        bar_arrive_id(4 + 2);   // EMPTY[2] seed
        curA = nxtA; curB = nxtB; tile = next;
    }
}

// ---------------------------------------------------------------------------
// Host launch
// ---------------------------------------------------------------------------
extern "C" void kernel_launch(void* const* d_in, const int* in_sizes, int n_in,
                              void* d_out, int out_size) {
    const float* x = (const float*)d_in[0];
    const float* W = (const float*)d_in[1];
    float* out = (float*)d_out;

    cudaFuncSetAttribute(gemm_kernel, cudaFuncAttributeMaxDynamicSharedMemorySize,
                         SMEM_TOTAL);

    int sms = 148;
    cudaDeviceGetAttribute(&sms, cudaDevAttrMultiProcessorCount, 0);

    prep_kernel<<<3072, 256>>>(W, x);
    gemm_kernel<<<2 * sms, 256, SMEM_TOTAL>>>(out);
}

// round 17
// speedup vs baseline: 1.0987x; 1.0987x over previous
#include <cuda.h>
#include <cuda_runtime.h>
#include <cuda_bf16.h>
#include <cuda_fp16.h>
#include <cstdint>

// ============================================================================
// y[8192,4096] = mean(|W|) * (x[8192,4096] @ sign(W)[4096,4096]^T)
// Round 14: R12 (best: 657.5us) with ONE delta — the produce step
// (EMPTY sync + cp.async of stage kt+2) hoisted from mid-kk-loop to the top
// of the kt iteration, ahead of the FULL sync. Prep as R11/R12.
// ============================================================================

#define M_TOTAL 8192
#define N_TOTAL 4096
#define K_TOTAL 4096

#define CTA_M 128
#define CTA_N 128
#define K_STEP 64
#define NKT (K_TOTAL / K_STEP)   // 64
#define STAGES 3

#define OFF_A 0
#define OFF_B 16384
#define STAGE_BYTES 32768
#define SMEM_TOTAL (STAGES * STAGE_BYTES)   // 98304 -> 2 CTAs/SM

// ---------------------------------------------------------------------------
// Device scratch (allocation-free rule: __device__ globals)
// ---------------------------------------------------------------------------
__device__ __align__(1024) __half g_Ah[(size_t)M_TOTAL * K_TOTAL];
__device__ __align__(1024) __half g_Bsign[(size_t)N_TOTAL * K_TOTAL];
__device__ float g_partials[1024];

// ---------------------------------------------------------------------------
// PTX helpers
// ---------------------------------------------------------------------------
__device__ __forceinline__ uint32_t smem_to_u32(const void* p) {
    uint32_t a;
    asm("{ .reg .u64 t; cvta.to.shared.u64 t, %1; cvt.u32.u64 %0, t; }" : "=r"(a) : "l"(p));
    return a;
}

__device__ __forceinline__ void cp_async16(uint32_t dst, const void* src) {
    asm volatile("cp.async.cg.shared.global [%0], [%1], 16;" :: "r"(dst), "l"(src) : "memory");
}
__device__ __forceinline__ void cp_commit() {
    asm volatile("cp.async.commit_group;" ::: "memory");
}
template <int N>
__device__ __forceinline__ void cp_wait() {
    asm volatile("cp.async.wait_group %0;" :: "n"(N) : "memory");
}

// Named barriers: 256 non-blocking arrivals + 256 blocking syncs = count 512.
__device__ __forceinline__ void bar_arrive_id(uint32_t id) {
    asm volatile("bar.arrive %0, 512;" :: "r"(id));
}
__device__ __forceinline__ void bar_sync_id(uint32_t id) {
    asm volatile("bar.sync %0, 512;" :: "r"(id) : "memory");
}

__device__ __forceinline__ void ldmatrix_x4(uint32_t& r0, uint32_t& r1,
                                            uint32_t& r2, uint32_t& r3, uint32_t addr) {
    asm volatile("ldmatrix.sync.aligned.m8n8.x4.shared.b16 {%0,%1,%2,%3}, [%4];"
                 : "=r"(r0), "=r"(r1), "=r"(r2), "=r"(r3) : "r"(addr));
}

__device__ __forceinline__ void mma16816(float& d0, float& d1, float& d2, float& d3,
                                         uint32_t a0, uint32_t a1, uint32_t a2, uint32_t a3,
                                         uint32_t b0, uint32_t b1) {
    asm volatile(
        "mma.sync.aligned.m16n8k16.row.col.f32.f16.f16.f32 "
        "{%0,%1,%2,%3}, {%4,%5,%6,%7}, {%8,%9}, {%0,%1,%2,%3};"
        : "+f"(d0), "+f"(d1), "+f"(d2), "+f"(d3)
        : "r"(a0), "r"(a1), "r"(a2), "r"(a3), "r"(b0), "r"(b1));
}

// ---------------------------------------------------------------------------
// Merged prep kernel (R11), grid 3072 x 256
// ---------------------------------------------------------------------------
__global__ void prep_kernel(const float* __restrict__ W, const float* __restrict__ x) {
    if (blockIdx.x < 1024) {
        __shared__ float sdata[256];
        const size_t base4 = (size_t)blockIdx.x * 4096;
        float s = 0.0f;
        #pragma unroll 4
        for (int it = 0; it < 16; it++) {
            size_t i = base4 + threadIdx.x + it * 256;
            float4 v = reinterpret_cast<const float4*>(W)[i];
            s += fabsf(v.x) + fabsf(v.y) + fabsf(v.z) + fabsf(v.w);
            float sx = (v.x > 0.0f) ? 1.0f : ((v.x < 0.0f) ? -1.0f : 0.0f);
            float sy = (v.y > 0.0f) ? 1.0f : ((v.y < 0.0f) ? -1.0f : 0.0f);
            float sz = (v.z > 0.0f) ? 1.0f : ((v.z < 0.0f) ? -1.0f : 0.0f);
            float sw = (v.w > 0.0f) ? 1.0f : ((v.w < 0.0f) ? -1.0f : 0.0f);
            ushort4 o = make_ushort4(__half_as_ushort(__float2half(sx)),
                                     __half_as_ushort(__float2half(sy)),
                                     __half_as_ushort(__float2half(sz)),
                                     __half_as_ushort(__float2half(sw)));
            reinterpret_cast<ushort4*>(g_Bsign)[i] = o;
        }
        sdata[threadIdx.x] = s;
        __syncthreads();
        for (int off = 128; off > 0; off >>= 1) {
            if (threadIdx.x < off) sdata[threadIdx.x] += sdata[threadIdx.x + off];
            __syncthreads();
        }
        if (threadIdx.x == 0) g_partials[blockIdx.x] = sdata[0];
    } else {
        const size_t base4 = (size_t)(blockIdx.x - 1024) * 4096;
        #pragma unroll 4
        for (int it = 0; it < 16; it++) {
            size_t i = base4 + threadIdx.x + it * 256;
            float4 v = reinterpret_cast<const float4*>(x)[i];
            ushort4 hv = make_ushort4(__half_as_ushort(__float2half_rn(v.x)),
                                      __half_as_ushort(__float2half_rn(v.y)),
                                      __half_as_ushort(__float2half_rn(v.z)),
                                      __half_as_ushort(__float2half_rn(v.w)));
            reinterpret_cast<ushort4*>(g_Ah)[i] = hv;
        }
    }
}

// ---------------------------------------------------------------------------
// GEMM kernel: CTA 128x128, 8 warps (2M x 4N), warp tile 64x32, K_STEP 64
// FULL[s] = named barrier 1+s, EMPTY[s] = named barrier 4+s (count 512).
// ---------------------------------------------------------------------------
__global__ void __launch_bounds__(256, 2) gemm_kernel(float* __restrict__ out) {
    extern __shared__ __align__(128) char smem[];
    const uint32_t smem_base = smem_to_u32(smem);

    const int tid = threadIdx.x;
    const int lane = tid & 31;
    const int wid = tid >> 5;
    const int wm = wid & 1;
    const int wn = wid >> 1;
    const int ntile = blockIdx.x;
    const int mtile = blockIdx.y;

    // ---- cp.async mapping (R10) ----
    const int cquad = tid & 7;
    const int row0 = tid >> 3;
    const uint32_t csw16 = (uint32_t)((cquad ^ (row0 & 7)) * 16);
    const char* pA = (const char*)g_Ah +
                     (size_t)(mtile * 128 + row0) * 8192 + cquad * 16;
    const char* pB = (const char*)g_Bsign +
                     (size_t)(ntile * 128 + row0) * 8192 + cquad * 16;
    const uint32_t dA = (uint32_t)(OFF_A + row0 * 128) + csw16;
    const uint32_t dB = (uint32_t)(OFF_B + row0 * 128) + csw16;

    auto load_stage = [&](int s, int kt) {
        const uint32_t st = smem_base + s * STAGE_BYTES;
        const size_t kb = (size_t)kt * 128;
        #pragma unroll
        for (int i = 0; i < 4; i++)
            cp_async16(st + dA + i * 32 * 128, pA + (size_t)i * 32 * 8192 + kb);
        #pragma unroll
        for (int i = 0; i < 4; i++)
            cp_async16(st + dB + i * 32 * 128, pB + (size_t)i * 32 * 8192 + kb);
        cp_commit();
    };

    // ---- ldmatrix per-lane addressing (R10) ----
    const uint32_t lo7 = (uint32_t)(lane & 7);
    const uint32_t aHi = (uint32_t)(lane >> 4);
    const uint32_t bHi = (uint32_t)((lane >> 3) & 1);
    uint32_t aRowOff[4];
    #pragma unroll
    for (int i = 0; i < 4; i++)
        aRowOff[i] = (uint32_t)(OFF_A + (wm * 64 + i * 16 + (lane & 15)) * 128);
    uint32_t bRowOff[2];
    #pragma unroll
    for (int j2 = 0; j2 < 2; j2++)
        bRowOff[j2] = (uint32_t)(OFF_B + (wn * 32 + (lane & 7) +
                                          ((lane >> 4) & 1) * 8 + j2 * 16) * 128);

    float acc[4][4][4];
    #pragma unroll
    for (int i = 0; i < 4; i++)
        #pragma unroll
        for (int j = 0; j < 4; j++)
            #pragma unroll
            for (int r = 0; r < 4; r++) acc[i][j][r] = 0.0f;

    // ---- prologue: stages 0 and 1; seed FULL0 and EMPTY2 ----
    load_stage(0, 0);
    load_stage(1, 1);
    cp_wait<1>();                 // group 0 (stage 0) complete for this thread
    bar_arrive_id(1 + 0);         // FULL[0]
    bar_arrive_id(4 + 2);         // EMPTY[2] seed

    int s_cons = 0;

    // ---- main loop ----
    for (int kt = 0; kt < NKT; kt++) {
        int s_load = s_cons + 2; if (s_load >= STAGES) s_load -= STAGES;
        int s_next = s_cons + 1; if (s_next >= STAGES) s_next -= STAGES;

        // ---- produce step hoisted to TOP (the one delta vs R12) ----
        if (kt + 2 < NKT) {
            bar_sync_id(4 + (uint32_t)s_load);   // EMPTY[s_load]: readers done @kt-1
            load_stage(s_load, kt + 2);           // commits a group
        } else {
            cp_commit();                          // empty group keeps accounting
        }

        bar_sync_id(1 + (uint32_t)s_cons);       // FULL[s_cons]: kt's data visible
        const uint32_t st = smem_base + s_cons * STAGE_BYTES;

        // ---- first half: kk = 0,1 ----
        #pragma unroll
        for (int kk = 0; kk < 2; kk++) {
            const uint32_t aC = ((uint32_t)(kk * 2) + aHi) ^ lo7;
            const uint32_t bC = ((uint32_t)(kk * 2) + bHi) ^ lo7;
            uint32_t bq[8];
            #pragma unroll
            for (int j2 = 0; j2 < 2; j2++)
                ldmatrix_x4(bq[4 * j2], bq[4 * j2 + 1], bq[4 * j2 + 2], bq[4 * j2 + 3],
                            st + bRowOff[j2] + bC * 16);
            #pragma unroll
            for (int i = 0; i < 4; i++) {
                uint32_t a0, a1, a2, a3;
                ldmatrix_x4(a0, a1, a2, a3, st + aRowOff[i] + aC * 16);
                #pragma unroll
                for (int j = 0; j < 4; j++) {
                    mma16816(acc[i][j][0], acc[i][j][1], acc[i][j][2], acc[i][j][3],
                             a0, a1, a2, a3, bq[2 * j], bq[2 * j + 1]);
                }
            }
        }

        // ---- mid: confirm stage kt+1 arrived ----
        cp_wait<1>();                             // my chunks for kt+1 complete
        bar_arrive_id(1 + (uint32_t)s_next);      // FULL[kt+1]

        // ---- second half: kk = 2,3 ----
        #pragma unroll
        for (int kk = 2; kk < 4; kk++) {
            const uint32_t aC = ((uint32_t)(kk * 2) + aHi) ^ lo7;
            const uint32_t bC = ((uint32_t)(kk * 2) + bHi) ^ lo7;
            uint32_t bq[8];
            #pragma unroll
            for (int j2 = 0; j2 < 2; j2++)
                ldmatrix_x4(bq[4 * j2], bq[4 * j2 + 1], bq[4 * j2 + 2], bq[4 * j2 + 3],
                            st + bRowOff[j2] + bC * 16);
            #pragma unroll
            for (int i = 0; i < 4; i++) {
                uint32_t a0, a1, a2, a3;
                ldmatrix_x4(a0, a1, a2, a3, st + aRowOff[i] + aC * 16);
                #pragma unroll
                for (int j = 0; j < 4; j++) {
                    mma16816(acc[i][j][0], acc[i][j][1], acc[i][j][2], acc[i][j][3],
                             a0, a1, a2, a3, bq[2 * j], bq[2 * j + 1]);
                }
            }
        }

        bar_arrive_id(4 + (uint32_t)s_cons);      // EMPTY[s_cons]: done reading kt
        s_cons = s_next;
    }
    cp_wait<0>();

    // ---- scale reduction (R11; deterministic order) ----
    __syncthreads();
    float* sred = reinterpret_cast<float*>(smem);
    {
        float s = 0.0f;
        #pragma unroll
        for (int i = 0; i < 4; i++) s += g_partials[tid * 4 + i];
        sred[tid] = s;
    }
    __syncthreads();
    for (int off = 128; off > 0; off >>= 1) {
        if (tid < off) sred[tid] += sred[tid + off];
        __syncthreads();
    }
    const float scl = sred[0] * (1.0f / 16777216.0f);

    // ---- epilogue: scale + store ----
    const int mbase = mtile * 128 + wm * 64 + (lane >> 2);
    const int nbase = ntile * 128 + wn * 32 + (lane & 3) * 2;
    #pragma unroll
    for (int i = 0; i < 4; i++) {
        const int r0 = mbase + i * 16;
        #pragma unroll
        for (int j = 0; j < 4; j++) {
            const int c = nbase + j * 8;
            float2 v0 = make_float2(acc[i][j][0] * scl, acc[i][j][1] * scl);
            float2 v1 = make_float2(acc[i][j][2] * scl, acc[i][j][3] * scl);
            *reinterpret_cast<float2*>(out + (size_t)r0 * N_TOTAL + c) = v0;
            *reinterpret_cast<float2*>(out + (size_t)(r0 + 8) * N_TOTAL + c) = v1;
        }
    }
}

// ---------------------------------------------------------------------------
// Host launch
// ---------------------------------------------------------------------------
extern "C" void kernel_launch(void* const* d_in, const int* in_sizes, int n_in,
                              void* d_out, int out_size) {
    const float* x = (const float*)d_in[0];
    const float* W = (const float*)d_in[1];
    float* out = (float*)d_out;

    cudaFuncSetAttribute(gemm_kernel, cudaFuncAttributeMaxDynamicSharedMemorySize,
                         SMEM_TOTAL);

    prep_kernel<<<3072, 256>>>(W, x);
    gemm_kernel<<<dim3(N_TOTAL / CTA_N, M_TOTAL / CTA_M, 1), 256, SMEM_TOTAL>>>(out);
}